// round 2
// baseline (speedup 1.0000x reference)
#include <cuda_runtime.h>

#define ALPHA 0.2f
#define NEG_BIG (-9000000000000000.0f)

#define NB 16
#define NN 1024
#define NF 256

// Scratch (device globals: allocation-free rule)
__device__ float g_h[NB * NN * NF];           // 64 MB: h = x @ W
__device__ float g_el[NB * NN];
__device__ float g_er[NB * NN];
__device__ float g_P[(size_t)NB * NN * NN];   // 64 MB: softmaxed attention

// ---------------------------------------------------------------------------
// Generic tiled SGEMM: C[M,Nd] = A[M,K] @ B[K,Nd], row-major, optional batch.
// BM=128, BN=64, BK=16, 256 threads, TM=8, TN=4 (32 outputs/thread).
// Requires M%128==0, Nd%64==0, K%16==0 (all shapes here satisfy this).
// ---------------------------------------------------------------------------
#define BM 128
#define BN 64
#define BK 16
#define TM 8
#define TN 4

__global__ __launch_bounds__(256) void sgemm_kernel(
    const float* __restrict__ A, const float* __restrict__ B,
    float* __restrict__ C, int M, int Nd, int K,
    long long strideA, long long strideB, long long strideC)
{
    __shared__ float As[BK][BM];
    __shared__ float Bs[BK][BN + 4];

    const int bz = blockIdx.z;
    A += bz * strideA;
    B += bz * strideB;
    C += bz * strideC;

    const int bm = blockIdx.x * BM;
    const int bn = blockIdx.y * BN;
    const int tid = threadIdx.x;
    const int tx = tid % (BN / TN);   // 0..15
    const int ty = tid / (BN / TN);   // 0..15

    float acc[TM][TN];
#pragma unroll
    for (int i = 0; i < TM; i++)
#pragma unroll
        for (int j = 0; j < TN; j++) acc[i][j] = 0.f;

    for (int k0 = 0; k0 < K; k0 += BK) {
        // Load A tile (BM x BK) as float4, store transposed As[k][m]
#pragma unroll
        for (int i = 0; i < (BM * BK) / (256 * 4); i++) {
            int f = tid + i * 256;            // float4 index, 0..511
            int row = f / (BK / 4);           // 0..127
            int c4 = f % (BK / 4);            // 0..3
            float4 v = *(const float4*)&A[(long long)(bm + row) * K + k0 + c4 * 4];
            As[c4 * 4 + 0][row] = v.x;
            As[c4 * 4 + 1][row] = v.y;
            As[c4 * 4 + 2][row] = v.z;
            As[c4 * 4 + 3][row] = v.w;
        }
        // Load B tile (BK x BN) as float4, direct layout
        {
            int row = tid / (BN / 4);         // 0..15
            int c4 = tid % (BN / 4);          // 0..15
            float4 v = *(const float4*)&B[(long long)(k0 + row) * Nd + bn + c4 * 4];
            *(float4*)&Bs[row][c4 * 4] = v;
        }
        __syncthreads();

#pragma unroll
        for (int k = 0; k < BK; k++) {
            float ar[TM], br[TN];
#pragma unroll
            for (int i = 0; i < TM; i++) ar[i] = As[k][ty * TM + i];
#pragma unroll
            for (int j = 0; j < TN; j++) br[j] = Bs[k][tx * TN + j];
#pragma unroll
            for (int i = 0; i < TM; i++)
#pragma unroll
                for (int j = 0; j < TN; j++) acc[i][j] += ar[i] * br[j];
        }
        __syncthreads();
    }

#pragma unroll
    for (int i = 0; i < TM; i++) {
        float4 v = make_float4(acc[i][0], acc[i][1], acc[i][2], acc[i][3]);
        *(float4*)&C[(long long)(bm + ty * TM + i) * Nd + bn + tx * TN] = v;
    }
}

// ---------------------------------------------------------------------------
// el[row] = h[row,:] . a[0:256],  er[row] = h[row,:] . a[256:512]
// One block (256 threads) per row.
// ---------------------------------------------------------------------------
__global__ __launch_bounds__(256) void rowdot_kernel(const float* __restrict__ a)
{
    int row = blockIdx.x;
    int tid = threadIdx.x;
    float hv = g_h[(size_t)row * NF + tid];
    float l = hv * a[tid];
    float r = hv * a[NF + tid];
#pragma unroll
    for (int o = 16; o > 0; o >>= 1) {
        l += __shfl_xor_sync(0xffffffffu, l, o);
        r += __shfl_xor_sync(0xffffffffu, r, o);
    }
    __shared__ float sl[8], sr[8];
    if ((tid & 31) == 0) { sl[tid >> 5] = l; sr[tid >> 5] = r; }
    __syncthreads();
    if (tid == 0) {
        float L = 0.f, R = 0.f;
#pragma unroll
        for (int w = 0; w < 8; w++) { L += sl[w]; R += sr[w]; }
        g_el[row] = L;
        g_er[row] = R;
    }
}

// ---------------------------------------------------------------------------
// Per-row masked leaky-relu + softmax: P[row, :] over 1024 columns.
// One block (256 threads) per row; each thread holds 4 columns in registers.
// adj is read exactly once.
// ---------------------------------------------------------------------------
__global__ __launch_bounds__(256) void attn_softmax_kernel(const int* __restrict__ adj)
{
    int row = blockIdx.x;          // b*NN + i
    int b = row >> 10;
    int tid = threadIdx.x;
    float eli = g_el[row];
    const int* adjr = adj + (size_t)row * NN;
    const float* err = g_er + b * NN;

    float ev[4];
    float mx = -3.4e38f;
#pragma unroll
    for (int t = 0; t < 4; t++) {
        int j = t * 256 + tid;
        float e = eli + err[j];
        e = e > 0.f ? e : ALPHA * e;            // leaky_relu
        if (adjr[j] <= 0) e = NEG_BIG;          // mask AFTER leaky (matches ref)
        ev[t] = e;
        mx = fmaxf(mx, e);
    }

    __shared__ float sred[8];
#pragma unroll
    for (int o = 16; o > 0; o >>= 1) mx = fmaxf(mx, __shfl_xor_sync(0xffffffffu, mx, o));
    if ((tid & 31) == 0) sred[tid >> 5] = mx;
    __syncthreads();
    mx = sred[0];
#pragma unroll
    for (int w = 1; w < 8; w++) mx = fmaxf(mx, sred[w]);
    __syncthreads();   // before reusing sred

    float s = 0.f;
    float pv[4];
#pragma unroll
    for (int t = 0; t < 4; t++) { pv[t] = __expf(ev[t] - mx); s += pv[t]; }
#pragma unroll
    for (int o = 16; o > 0; o >>= 1) s += __shfl_xor_sync(0xffffffffu, s, o);
    if ((tid & 31) == 0) sred[tid >> 5] = s;
    __syncthreads();
    s = 0.f;
#pragma unroll
    for (int w = 0; w < 8; w++) s += sred[w];

    float inv = 1.0f / s;
    float* Pr = g_P + (size_t)row * NN;
#pragma unroll
    for (int t = 0; t < 4; t++) Pr[t * 256 + tid] = pv[t] * inv;
}

// ---------------------------------------------------------------------------
extern "C" void kernel_launch(void* const* d_in, const int* in_sizes, int n_in,
                              void* d_out, int out_size)
{
    const float* x   = (const float*)d_in[0];   // (16,1024,256) f32
    const int*   adj = (const int*)d_in[1];     // (16,1024,1024) i32
    const float* W   = (const float*)d_in[2];   // (256,256) f32
    const float* a   = (const float*)d_in[3];   // (512,1) f32
    float* out = (float*)d_out;                 // (16,1024,256) f32

    float *h, *P;
    cudaGetSymbolAddress((void**)&h, g_h);
    cudaGetSymbolAddress((void**)&P, g_P);

    // 1) h = x @ W   (M=16384, N=256, K=256)
    {
        dim3 grid((NB * NN) / BM, NF / BN, 1);
        sgemm_kernel<<<grid, 256>>>(x, W, h, NB * NN, NF, NF, 0, 0, 0);
    }
    // 2) el, er
    rowdot_kernel<<<NB * NN, 256>>>(a);
    // 3) masked softmax -> P
    attn_softmax_kernel<<<NB * NN, 256>>>(adj);
    // 4) out = P @ h   (batched: per-b M=1024, N=256, K=1024)
    {
        dim3 grid(NN / BM, NF / BN, NB);
        sgemm_kernel<<<grid, 256>>>(P, h, out, NN, NF, NN,
                                    (long long)NN * NN, (long long)NN * NF,
                                    (long long)NN * NF);
    }
}

// round 4
// speedup vs baseline: 1.2960x; 1.2960x over previous
#include <cuda_runtime.h>
#include <cstdint>

#define ALPHA 0.2f
#define NEG_BIG (-9000000000000000.0f)

#define NB 16
#define NN 1024
#define NF 256

// Scratch (device globals: allocation-free rule)
__device__ float g_h[NB * NN * NF];           // 64 MB: h = x @ W
__device__ float g_el[NB * NN];
__device__ float g_er[NB * NN];
__device__ float g_P[(size_t)NB * NN * NN];   // 64 MB: softmaxed attention

// ---------------------------------------------------------------------------
// SIMT SGEMM (kept for h = x@W, exact fp32): BM=128,BN=64,BK=16
// ---------------------------------------------------------------------------
#define BM 128
#define BN 64
#define BK 16
#define TM 8
#define TN 4

__global__ __launch_bounds__(256) void sgemm_kernel(
    const float* __restrict__ A, const float* __restrict__ B,
    float* __restrict__ C, int M, int Nd, int K,
    long long strideA, long long strideB, long long strideC)
{
    __shared__ float As[BK][BM];
    __shared__ float Bs[BK][BN + 4];

    const int bz = blockIdx.z;
    A += bz * strideA;
    B += bz * strideB;
    C += bz * strideC;

    const int bm = blockIdx.x * BM;
    const int bn = blockIdx.y * BN;
    const int tid = threadIdx.x;
    const int tx = tid % (BN / TN);
    const int ty = tid / (BN / TN);

    float acc[TM][TN];
#pragma unroll
    for (int i = 0; i < TM; i++)
#pragma unroll
        for (int j = 0; j < TN; j++) acc[i][j] = 0.f;

    for (int k0 = 0; k0 < K; k0 += BK) {
#pragma unroll
        for (int i = 0; i < (BM * BK) / (256 * 4); i++) {
            int f = tid + i * 256;
            int row = f / (BK / 4);
            int c4 = f % (BK / 4);
            float4 v = *(const float4*)&A[(long long)(bm + row) * K + k0 + c4 * 4];
            As[c4 * 4 + 0][row] = v.x;
            As[c4 * 4 + 1][row] = v.y;
            As[c4 * 4 + 2][row] = v.z;
            As[c4 * 4 + 3][row] = v.w;
        }
        {
            int row = tid / (BN / 4);
            int c4 = tid % (BN / 4);
            float4 v = *(const float4*)&B[(long long)(k0 + row) * Nd + bn + c4 * 4];
            *(float4*)&Bs[row][c4 * 4] = v;
        }
        __syncthreads();

#pragma unroll
        for (int k = 0; k < BK; k++) {
            float ar[TM], br[TN];
#pragma unroll
            for (int i = 0; i < TM; i++) ar[i] = As[k][ty * TM + i];
#pragma unroll
            for (int j = 0; j < TN; j++) br[j] = Bs[k][tx * TN + j];
#pragma unroll
            for (int i = 0; i < TM; i++)
#pragma unroll
                for (int j = 0; j < TN; j++) acc[i][j] += ar[i] * br[j];
        }
        __syncthreads();
    }

#pragma unroll
    for (int i = 0; i < TM; i++) {
        float4 v = make_float4(acc[i][0], acc[i][1], acc[i][2], acc[i][3]);
        *(float4*)&C[(long long)(bm + ty * TM + i) * Nd + bn + tx * TN] = v;
    }
}

// ---------------------------------------------------------------------------
// Tensor-core tf32 GEMM for out = P @ h (batched).
// Block tile 128x128, BK=32, 256 threads = 8 warps (2x4), warp tile 64x32.
// mma.sync.aligned.m16n8k8.row.col.f32.tf32.tf32.f32
// ---------------------------------------------------------------------------
__device__ __forceinline__ uint32_t f2tf32(float f) {
    uint32_t r;
    asm("cvt.rna.tf32.f32 %0, %1;" : "=r"(r) : "f"(f));
    return r;
}

__global__ __launch_bounds__(256, 2) void mma_ph_kernel(
    const float* __restrict__ Pg, const float* __restrict__ Hg,
    float* __restrict__ Cg)
{
    __shared__ uint32_t As[128][36];   // A tile: 128 x 32 (padded stride 36)
    __shared__ uint32_t Bs[32][136];   // B tile: 32 x 128 (padded stride 136)

    const int b = blockIdx.z;
    const float* A = Pg + (size_t)b * NN * NN;   // [1024,1024]
    const float* B = Hg + (size_t)b * NN * NF;   // [1024,256]
    float* C = Cg + (size_t)b * NN * NF;

    const int bm = blockIdx.x * 128;
    const int bn = blockIdx.y * 128;
    const int tid = threadIdx.x;
    const int warp = tid >> 5;
    const int lane = tid & 31;
    const int wm = warp >> 2;        // 0..1
    const int wn = warp & 3;         // 0..3
    const int g = lane >> 2;         // groupID 0..7
    const int t = lane & 3;          // threadID-in-group 0..3

    float acc[4][4][4];
#pragma unroll
    for (int mi = 0; mi < 4; mi++)
#pragma unroll
        for (int ni = 0; ni < 4; ni++)
#pragma unroll
            for (int r = 0; r < 4; r++) acc[mi][ni][r] = 0.f;

    for (int k0 = 0; k0 < NN; k0 += 32) {
        // Load A tile (128x32): 1024 float4 / 256 threads = 4 each
#pragma unroll
        for (int j = 0; j < 4; j++) {
            int i = tid + j * 256;
            int row = i >> 3;
            int c4 = (i & 7) * 4;
            float4 v = *(const float4*)&A[(size_t)(bm + row) * NN + k0 + c4];
            uint4 u = make_uint4(f2tf32(v.x), f2tf32(v.y), f2tf32(v.z), f2tf32(v.w));
            *(uint4*)&As[row][c4] = u;
        }
        // Load B tile (32x128): 1024 float4 / 256 threads = 4 each
#pragma unroll
        for (int j = 0; j < 4; j++) {
            int i = tid + j * 256;
            int row = i >> 5;
            int c4 = (i & 31) * 4;
            float4 v = *(const float4*)&B[(size_t)(k0 + row) * NF + bn + c4];
            uint4 u = make_uint4(f2tf32(v.x), f2tf32(v.y), f2tf32(v.z), f2tf32(v.w));
            *(uint4*)&Bs[row][c4] = u;
        }
        __syncthreads();

#pragma unroll
        for (int kc = 0; kc < 4; kc++) {
            const int kk = kc * 8;
            uint32_t af[4][4], bf[4][2];
#pragma unroll
            for (int mi = 0; mi < 4; mi++) {
                int m0 = wm * 64 + mi * 16;
                af[mi][0] = As[m0 + g][kk + t];          // row g,   col t
                af[mi][1] = As[m0 + g + 8][kk + t];      // row g+8, col t
                af[mi][2] = As[m0 + g][kk + t + 4];      // row g,   col t+4
                af[mi][3] = As[m0 + g + 8][kk + t + 4];  // row g+8, col t+4
            }
#pragma unroll
            for (int ni = 0; ni < 4; ni++) {
                int n0 = wn * 32 + ni * 8;
                bf[ni][0] = Bs[kk + t][n0 + g];          // k t,   n g
                bf[ni][1] = Bs[kk + t + 4][n0 + g];      // k t+4, n g
            }
#pragma unroll
            for (int mi = 0; mi < 4; mi++)
#pragma unroll
                for (int ni = 0; ni < 4; ni++) {
                    asm volatile(
                        "mma.sync.aligned.m16n8k8.row.col.f32.tf32.tf32.f32 "
                        "{%0,%1,%2,%3}, {%4,%5,%6,%7}, {%8,%9}, {%0,%1,%2,%3};"
                        : "+f"(acc[mi][ni][0]), "+f"(acc[mi][ni][1]),
                          "+f"(acc[mi][ni][2]), "+f"(acc[mi][ni][3])
                        : "r"(af[mi][0]), "r"(af[mi][1]), "r"(af[mi][2]), "r"(af[mi][3]),
                          "r"(bf[ni][0]), "r"(bf[ni][1]));
                }
        }
        __syncthreads();
    }

    // Epilogue: c0/c1 -> (row g, cols 2t,2t+1); c2/c3 -> (row g+8)
#pragma unroll
    for (int mi = 0; mi < 4; mi++) {
#pragma unroll
        for (int ni = 0; ni < 4; ni++) {
            int row0 = bm + wm * 64 + mi * 16 + g;
            int col = bn + wn * 32 + ni * 8 + t * 2;
            *(float2*)&C[(size_t)row0 * NF + col] =
                make_float2(acc[mi][ni][0], acc[mi][ni][1]);
            *(float2*)&C[(size_t)(row0 + 8) * NF + col] =
                make_float2(acc[mi][ni][2], acc[mi][ni][3]);
        }
    }
}

// ---------------------------------------------------------------------------
// el[row] = h[row,:] . a[0:256],  er[row] = h[row,:] . a[256:512]
// ---------------------------------------------------------------------------
__global__ __launch_bounds__(256) void rowdot_kernel(const float* __restrict__ a)
{
    int row = blockIdx.x;
    int tid = threadIdx.x;
    float hv = g_h[(size_t)row * NF + tid];
    float l = hv * a[tid];
    float r = hv * a[NF + tid];
#pragma unroll
    for (int o = 16; o > 0; o >>= 1) {
        l += __shfl_xor_sync(0xffffffffu, l, o);
        r += __shfl_xor_sync(0xffffffffu, r, o);
    }
    __shared__ float sl[8], sr[8];
    if ((tid & 31) == 0) { sl[tid >> 5] = l; sr[tid >> 5] = r; }
    __syncthreads();
    if (tid == 0) {
        float L = 0.f, R = 0.f;
#pragma unroll
        for (int w = 0; w < 8; w++) { L += sl[w]; R += sr[w]; }
        g_el[row] = L;
        g_er[row] = R;
    }
}

// ---------------------------------------------------------------------------
// Per-row masked leaky-relu + softmax
// ---------------------------------------------------------------------------
__global__ __launch_bounds__(256) void attn_softmax_kernel(const int* __restrict__ adj)
{
    int row = blockIdx.x;
    int b = row >> 10;
    int tid = threadIdx.x;
    float eli = g_el[row];
    const int* adjr = adj + (size_t)row * NN;
    const float* err = g_er + b * NN;

    float ev[4];
    float mx = -3.4e38f;
#pragma unroll
    for (int t = 0; t < 4; t++) {
        int j = t * 256 + tid;
        float e = eli + err[j];
        e = e > 0.f ? e : ALPHA * e;
        if (adjr[j] <= 0) e = NEG_BIG;
        ev[t] = e;
        mx = fmaxf(mx, e);
    }

    __shared__ float sred[8];
#pragma unroll
    for (int o = 16; o > 0; o >>= 1) mx = fmaxf(mx, __shfl_xor_sync(0xffffffffu, mx, o));
    if ((tid & 31) == 0) sred[tid >> 5] = mx;
    __syncthreads();
    mx = sred[0];
#pragma unroll
    for (int w = 1; w < 8; w++) mx = fmaxf(mx, sred[w]);
    __syncthreads();

    float s = 0.f;
    float pv[4];
#pragma unroll
    for (int t = 0; t < 4; t++) { pv[t] = __expf(ev[t] - mx); s += pv[t]; }
#pragma unroll
    for (int o = 16; o > 0; o >>= 1) s += __shfl_xor_sync(0xffffffffu, s, o);
    if ((tid & 31) == 0) sred[tid >> 5] = s;
    __syncthreads();
    s = 0.f;
#pragma unroll
    for (int w = 0; w < 8; w++) s += sred[w];

    float inv = 1.0f / s;
    float* Pr = g_P + (size_t)row * NN;
#pragma unroll
    for (int t = 0; t < 4; t++) Pr[t * 256 + tid] = pv[t] * inv;
}

// ---------------------------------------------------------------------------
extern "C" void kernel_launch(void* const* d_in, const int* in_sizes, int n_in,
                              void* d_out, int out_size)
{
    const float* x   = (const float*)d_in[0];   // (16,1024,256) f32
    const int*   adj = (const int*)d_in[1];     // (16,1024,1024) i32
    const float* W   = (const float*)d_in[2];   // (256,256) f32
    const float* a   = (const float*)d_in[3];   // (512,1) f32
    float* out = (float*)d_out;                 // (16,1024,256) f32

    float *h, *P;
    cudaGetSymbolAddress((void**)&h, g_h);
    cudaGetSymbolAddress((void**)&P, g_P);

    // 1) h = x @ W  (exact fp32 — feeds softmax via el/er)
    {
        dim3 grid((NB * NN) / BM, NF / BN, 1);
        sgemm_kernel<<<grid, 256>>>(x, W, h, NB * NN, NF, NF, 0, 0, 0);
    }
    // 2) el, er
    rowdot_kernel<<<NB * NN, 256>>>(a);
    // 3) masked softmax -> P
    attn_softmax_kernel<<<NB * NN, 256>>>(adj);
    // 4) out = P @ h  (tf32 tensor cores)
    {
        dim3 grid(NN / 128, NF / 128, NB);
        mma_ph_kernel<<<grid, 256>>>(P, h, out);
    }
}

// round 7
// speedup vs baseline: 2.6823x; 2.0697x over previous
#include <cuda_runtime.h>
#include <cstdint>

#define ALPHA 0.2f
#define NEG_BIG (-9000000000000000.0f)

#define NB 16
#define NN 1024
#define NF 256

// Scratch (device globals: allocation-free rule)
__device__ float g_h[NB * NN * NF];           // 16 MB: h = x @ W
__device__ float g_el[NB * NN];
__device__ float g_er[NB * NN];
__device__ float g_wa[2 * NF];                // W @ a_l, W @ a_r
__device__ float g_P[(size_t)NB * NN * NN];   // 64 MB: softmaxed attention

// ---------------------------------------------------------------------------
// helpers
// ---------------------------------------------------------------------------
__device__ __forceinline__ uint32_t f2tf32(float f) {
    uint32_t r;
    asm("cvt.rna.tf32.f32 %0, %1;" : "=r"(r) : "f"(f));
    return r;
}
__device__ __forceinline__ void cpasync16(uint32_t dst, const float* src) {
    asm volatile("cp.async.cg.shared.global [%0], [%1], 16;" :: "r"(dst), "l"(src));
}

// smem tile geometry (floats)
#define AS_STRIDE 36
#define BS_STRIDE 136
#define AS_TILE (128 * AS_STRIDE)     // 4608
#define BS_TILE (32 * BS_STRIDE)      // 4352
#define STG_SIZE (AS_TILE + BS_TILE)  // 8960
#define SMEM_BYTES (2 * STG_SIZE * 4) // 71680

// ---------------------------------------------------------------------------
// tf32 tensor-core GEMM, cp.async double-buffered.
// C[M,N] = A[M,K] @ B[K,N]; block tile 128x128, BK=32, 256 thr = 8 warps (2x4),
// warp tile 64x32, mma.m16n8k8.tf32. Batched via blockIdx.z strides.
// ---------------------------------------------------------------------------
__global__ __launch_bounds__(256, 2) void mma_gemm_kernel(
    const float* __restrict__ Ag, const float* __restrict__ Bg,
    float* __restrict__ Cg, int K,
    long long strideA, long long strideB, long long strideC)
{
    extern __shared__ float smem[];

    const int bz = blockIdx.z;
    const float* A = Ag + bz * strideA;
    const float* B = Bg + bz * strideB;
    float* C = Cg + bz * strideC;

    const int lda = K;        // A is [M,K] row-major with ld = K
    const int ldb = NF;       // B is [K,256]
    const int ldc = NF;

    const int bm = blockIdx.x * 128;
    const int bn = blockIdx.y * 128;
    const int tid = threadIdx.x;
    const int warp = tid >> 5;
    const int lane = tid & 31;
    const int wm = warp >> 2;        // 0..1
    const int wn = warp & 3;         // 0..3
    const int g = lane >> 2;         // 0..7
    const int t = lane & 3;          // 0..3

    // per-thread load coordinates (A: 4 float4, B: 4 float4 per stage)
    int a_row[4], a_c4[4], b_row[4], b_c4[4];
#pragma unroll
    for (int j = 0; j < 4; j++) {
        int i = tid + j * 256;
        a_row[j] = i >> 3;  a_c4[j] = (i & 7) * 4;
        b_row[j] = i >> 5;  b_c4[j] = (i & 31) * 4;
    }

    uint32_t smem_u32;
    {
        void* p = (void*)smem;
        smem_u32 = (uint32_t)__cvta_generic_to_shared(p);
    }

    const int niter = K / 32;

    // issue stage-s loads for k0
    auto issue_stage = [&](int s, int k0) {
        uint32_t as_base = smem_u32 + (uint32_t)(s * STG_SIZE) * 4u;
        uint32_t bs_base = as_base + (uint32_t)AS_TILE * 4u;
#pragma unroll
        for (int j = 0; j < 4; j++) {
            cpasync16(as_base + (uint32_t)(a_row[j] * AS_STRIDE + a_c4[j]) * 4u,
                      &A[(size_t)(bm + a_row[j]) * lda + k0 + a_c4[j]]);
        }
#pragma unroll
        for (int j = 0; j < 4; j++) {
            cpasync16(bs_base + (uint32_t)(b_row[j] * BS_STRIDE + b_c4[j]) * 4u,
                      &B[(size_t)(k0 + b_row[j]) * ldb + bn + b_c4[j]]);
        }
        asm volatile("cp.async.commit_group;");
    };

    float acc[4][4][4];
#pragma unroll
    for (int mi = 0; mi < 4; mi++)
#pragma unroll
        for (int ni = 0; ni < 4; ni++)
#pragma unroll
            for (int r = 0; r < 4; r++) acc[mi][ni][r] = 0.f;

    issue_stage(0, 0);

    for (int it = 0; it < niter; it++) {
        if (it + 1 < niter) {
            issue_stage((it + 1) & 1, (it + 1) * 32);
            asm volatile("cp.async.wait_group 1;");
        } else {
            asm volatile("cp.async.wait_group 0;");
        }
        __syncthreads();

        const float* As = smem + (it & 1) * STG_SIZE;
        const float* Bs = As + AS_TILE;

#pragma unroll
        for (int kc = 0; kc < 4; kc++) {
            const int kk = kc * 8;
            uint32_t af[4][4], bf[4][2];
#pragma unroll
            for (int mi = 0; mi < 4; mi++) {
                int m0 = wm * 64 + mi * 16;
                af[mi][0] = f2tf32(As[(m0 + g) * AS_STRIDE + kk + t]);
                af[mi][1] = f2tf32(As[(m0 + g + 8) * AS_STRIDE + kk + t]);
                af[mi][2] = f2tf32(As[(m0 + g) * AS_STRIDE + kk + t + 4]);
                af[mi][3] = f2tf32(As[(m0 + g + 8) * AS_STRIDE + kk + t + 4]);
            }
#pragma unroll
            for (int ni = 0; ni < 4; ni++) {
                int n0 = wn * 32 + ni * 8;
                bf[ni][0] = f2tf32(Bs[(kk + t) * BS_STRIDE + n0 + g]);
                bf[ni][1] = f2tf32(Bs[(kk + t + 4) * BS_STRIDE + n0 + g]);
            }
#pragma unroll
            for (int mi = 0; mi < 4; mi++)
#pragma unroll
                for (int ni = 0; ni < 4; ni++) {
                    asm volatile(
                        "mma.sync.aligned.m16n8k8.row.col.f32.tf32.tf32.f32 "
                        "{%0,%1,%2,%3}, {%4,%5,%6,%7}, {%8,%9}, {%0,%1,%2,%3};"
                        : "+f"(acc[mi][ni][0]), "+f"(acc[mi][ni][1]),
                          "+f"(acc[mi][ni][2]), "+f"(acc[mi][ni][3])
                        : "r"(af[mi][0]), "r"(af[mi][1]), "r"(af[mi][2]), "r"(af[mi][3]),
                          "r"(bf[ni][0]), "r"(bf[ni][1]));
                }
        }
        __syncthreads();   // all warps done with this buffer before next cp.async overwrites
    }

#pragma unroll
    for (int mi = 0; mi < 4; mi++) {
#pragma unroll
        for (int ni = 0; ni < 4; ni++) {
            int row0 = bm + wm * 64 + mi * 16 + g;
            int col = bn + wn * 32 + ni * 8 + t * 2;
            *(float2*)&C[(size_t)row0 * ldc + col] =
                make_float2(acc[mi][ni][0], acc[mi][ni][1]);
            *(float2*)&C[(size_t)(row0 + 8) * ldc + col] =
                make_float2(acc[mi][ni][2], acc[mi][ni][3]);
        }
    }
}

// ---------------------------------------------------------------------------
// wa[sel][i] = sum_o W[i][o] * a[sel*256 + o]    (exact fp32, tiny)
// NOTE: sums over W's COLUMNS (o) — this was the R5 bug (had W transposed).
// grid 512 blocks (sel = blk>>8, i = blk&255), 256 threads
// ---------------------------------------------------------------------------
__global__ __launch_bounds__(256) void wa_kernel(
    const float* __restrict__ W, const float* __restrict__ a)
{
    int i = blockIdx.x & 255;
    int sel = blockIdx.x >> 8;
    int tid = threadIdx.x;
    float v = W[(size_t)i * NF + tid] * a[sel * NF + tid];
#pragma unroll
    for (int off = 16; off > 0; off >>= 1)
        v += __shfl_xor_sync(0xffffffffu, v, off);
    __shared__ float s[8];
    if ((tid & 31) == 0) s[tid >> 5] = v;
    __syncthreads();
    if (tid == 0) {
        float acc = 0.f;
#pragma unroll
        for (int w = 0; w < 8; w++) acc += s[w];
        g_wa[sel * NF + i] = acc;
    }
}

// ---------------------------------------------------------------------------
// el[row] = x[row,:] . wa_l,  er[row] = x[row,:] . wa_r   (exact fp32)
// ---------------------------------------------------------------------------
__global__ __launch_bounds__(256) void rowdot_x_kernel(const float* __restrict__ x)
{
    int row = blockIdx.x;
    int tid = threadIdx.x;
    float xv = x[(size_t)row * NF + tid];
    float l = xv * g_wa[tid];
    float r = xv * g_wa[NF + tid];
#pragma unroll
    for (int o = 16; o > 0; o >>= 1) {
        l += __shfl_xor_sync(0xffffffffu, l, o);
        r += __shfl_xor_sync(0xffffffffu, r, o);
    }
    __shared__ float sl[8], sr[8];
    if ((tid & 31) == 0) { sl[tid >> 5] = l; sr[tid >> 5] = r; }
    __syncthreads();
    if (tid == 0) {
        float L = 0.f, R = 0.f;
#pragma unroll
        for (int w = 0; w < 8; w++) { L += sl[w]; R += sr[w]; }
        g_el[row] = L;
        g_er[row] = R;
    }
}

// ---------------------------------------------------------------------------
// Per-row masked leaky-relu + softmax, vectorized (int4 / float4).
// One block (256 threads) per row; thread t owns cols 4t..4t+3.
// ---------------------------------------------------------------------------
__global__ __launch_bounds__(256) void attn_softmax_kernel(const int* __restrict__ adj)
{
    int row = blockIdx.x;
    int b = row >> 10;
    int tid = threadIdx.x;
    float eli = g_el[row];

    int4 av = *(const int4*)&adj[(size_t)row * NN + tid * 4];
    float4 ef = *(const float4*)&g_er[(size_t)b * NN + tid * 4];

    float ev[4];
    {
        float e0 = eli + ef.x, e1 = eli + ef.y, e2 = eli + ef.z, e3 = eli + ef.w;
        e0 = e0 > 0.f ? e0 : ALPHA * e0;
        e1 = e1 > 0.f ? e1 : ALPHA * e1;
        e2 = e2 > 0.f ? e2 : ALPHA * e2;
        e3 = e3 > 0.f ? e3 : ALPHA * e3;
        ev[0] = av.x > 0 ? e0 : NEG_BIG;
        ev[1] = av.y > 0 ? e1 : NEG_BIG;
        ev[2] = av.z > 0 ? e2 : NEG_BIG;
        ev[3] = av.w > 0 ? e3 : NEG_BIG;
    }
    float mx = fmaxf(fmaxf(ev[0], ev[1]), fmaxf(ev[2], ev[3]));

    __shared__ float sred[8];
#pragma unroll
    for (int o = 16; o > 0; o >>= 1) mx = fmaxf(mx, __shfl_xor_sync(0xffffffffu, mx, o));
    if ((tid & 31) == 0) sred[tid >> 5] = mx;
    __syncthreads();
    mx = sred[0];
#pragma unroll
    for (int w = 1; w < 8; w++) mx = fmaxf(mx, sred[w]);
    __syncthreads();

    float pv[4];
    float s = 0.f;
#pragma unroll
    for (int q = 0; q < 4; q++) { pv[q] = __expf(ev[q] - mx); s += pv[q]; }
#pragma unroll
    for (int o = 16; o > 0; o >>= 1) s += __shfl_xor_sync(0xffffffffu, s, o);
    if ((tid & 31) == 0) sred[tid >> 5] = s;
    __syncthreads();
    s = 0.f;
#pragma unroll
    for (int w = 0; w < 8; w++) s += sred[w];

    float inv = 1.0f / s;
    float4 p4 = make_float4(pv[0] * inv, pv[1] * inv, pv[2] * inv, pv[3] * inv);
    *(float4*)&g_P[(size_t)row * NN + tid * 4] = p4;
}

// ---------------------------------------------------------------------------
extern "C" void kernel_launch(void* const* d_in, const int* in_sizes, int n_in,
                              void* d_out, int out_size)
{
    const float* x   = (const float*)d_in[0];   // (16,1024,256) f32
    const int*   adj = (const int*)d_in[1];     // (16,1024,1024) i32
    const float* W   = (const float*)d_in[2];   // (256,256) f32
    const float* a   = (const float*)d_in[3];   // (512,1) f32
    float* out = (float*)d_out;                 // (16,1024,256) f32

    float *h, *P;
    cudaGetSymbolAddress((void**)&h, g_h);
    cudaGetSymbolAddress((void**)&P, g_P);

    cudaFuncSetAttribute(mma_gemm_kernel,
                         cudaFuncAttributeMaxDynamicSharedMemorySize, SMEM_BYTES);

    // 1) wa = W @ [a_l | a_r]   (exact)
    wa_kernel<<<512, 256>>>(W, a);
    // 2) el/er = x @ wa  (exact fp32 -> softmax numerics independent of tf32 h)
    rowdot_x_kernel<<<NB * NN, 256>>>(x);
    // 3) h = x @ W  (tf32 tensor cores; only feeds output GEMM)
    {
        dim3 grid((NB * NN) / 128, NF / 128, 1);
        mma_gemm_kernel<<<grid, 256, SMEM_BYTES>>>(x, W, h, NF, 0, 0, 0);
    }
    // 4) masked softmax -> P
    attn_softmax_kernel<<<NB * NN, 256>>>(adj);
    // 5) out = P @ h  (tf32 tensor cores)
    {
        dim3 grid(NN / 128, NF / 128, NB);
        mma_gemm_kernel<<<grid, 256, SMEM_BYTES>>>(P, h, out, NN,
                                                   (long long)NN * NN,
                                                   (long long)NN * NF,
                                                   (long long)NN * NF);
    }
}

// round 8
// speedup vs baseline: 2.8523x; 1.0634x over previous
#include <cuda_runtime.h>
#include <cstdint>

#define ALPHA 0.2f
#define NEG_BIG (-9000000000000000.0f)

#define NB 16
#define NN 1024
#define NF 256

// Scratch (device globals: allocation-free rule)
__device__ float g_h[NB * NN * NF];           // 16 MB: h = x @ W
__device__ float g_el[NB * NN];
__device__ float g_er[NB * NN];
__device__ float g_wa[2 * NF];                // W @ a_l, W @ a_r

// ---------------------------------------------------------------------------
// helpers
// ---------------------------------------------------------------------------
__device__ __forceinline__ uint32_t f2tf32(float f) {
    uint32_t r;
    asm("cvt.rna.tf32.f32 %0, %1;" : "=r"(r) : "f"(f));
    return r;
}
__device__ __forceinline__ void cpasync16(uint32_t dst, const void* src) {
    asm volatile("cp.async.cg.shared.global [%0], [%1], 16;" :: "r"(dst), "l"(src));
}

// smem tile geometry (32-bit words)
#define AS_STRIDE 36
#define BS_STRIDE 136
#define ADJ_STRIDE 32
#define AS_TILE (128 * AS_STRIDE)      // 4608
#define BS_TILE (32 * BS_STRIDE)       // 4352
#define ADJ_TILE (128 * ADJ_STRIDE)    // 4096

// plain GEMM smem (h = x@W)
#define G1_STG (AS_TILE + BS_TILE)
#define G1_SMEM_BYTES (2 * G1_STG * 4)             // 71680

// fused GEMM smem
#define FU_WORDS (2 * AS_TILE + 2 * BS_TILE + 2 * ADJ_TILE + 128)
#define FU_SMEM_BYTES (FU_WORDS * 4)               // 104960

// ---------------------------------------------------------------------------
// tf32 tensor-core GEMM, cp.async double-buffered (used for h = x@W).
// C[M,N] = A[M,K] @ B[K,N]; block 128x128, BK=32, 8 warps (2x4), warp 64x32.
// ---------------------------------------------------------------------------
__global__ __launch_bounds__(256, 2) void mma_gemm_kernel(
    const float* __restrict__ A, const float* __restrict__ B,
    float* __restrict__ C, int K)
{
    extern __shared__ float smem[];

    const int lda = K;
    const int ldb = NF;
    const int ldc = NF;

    const int bm = blockIdx.x * 128;
    const int bn = blockIdx.y * 128;
    const int tid = threadIdx.x;
    const int warp = tid >> 5;
    const int lane = tid & 31;
    const int wm = warp >> 2;
    const int wn = warp & 3;
    const int g = lane >> 2;
    const int t = lane & 3;

    int a_row[4], a_c4[4], b_row[4], b_c4[4];
#pragma unroll
    for (int j = 0; j < 4; j++) {
        int i = tid + j * 256;
        a_row[j] = i >> 3;  a_c4[j] = (i & 7) * 4;
        b_row[j] = i >> 5;  b_c4[j] = (i & 31) * 4;
    }

    uint32_t smem_u32 = (uint32_t)__cvta_generic_to_shared((void*)smem);
    const int niter = K / 32;

    auto issue_stage = [&](int s, int k0) {
        uint32_t as_base = smem_u32 + (uint32_t)(s * G1_STG) * 4u;
        uint32_t bs_base = as_base + (uint32_t)AS_TILE * 4u;
#pragma unroll
        for (int j = 0; j < 4; j++)
            cpasync16(as_base + (uint32_t)(a_row[j] * AS_STRIDE + a_c4[j]) * 4u,
                      &A[(size_t)(bm + a_row[j]) * lda + k0 + a_c4[j]]);
#pragma unroll
        for (int j = 0; j < 4; j++)
            cpasync16(bs_base + (uint32_t)(b_row[j] * BS_STRIDE + b_c4[j]) * 4u,
                      &B[(size_t)(k0 + b_row[j]) * ldb + bn + b_c4[j]]);
        asm volatile("cp.async.commit_group;");
    };

    float acc[4][4][4];
#pragma unroll
    for (int mi = 0; mi < 4; mi++)
#pragma unroll
        for (int ni = 0; ni < 4; ni++)
#pragma unroll
            for (int r = 0; r < 4; r++) acc[mi][ni][r] = 0.f;

    issue_stage(0, 0);

    for (int it = 0; it < niter; it++) {
        if (it + 1 < niter) {
            issue_stage((it + 1) & 1, (it + 1) * 32);
            asm volatile("cp.async.wait_group 1;");
        } else {
            asm volatile("cp.async.wait_group 0;");
        }
        __syncthreads();

        const float* As = smem + (it & 1) * G1_STG;
        const float* Bs = As + AS_TILE;

#pragma unroll
        for (int kc = 0; kc < 4; kc++) {
            const int kk = kc * 8;
            uint32_t af[4][4], bf[4][2];
#pragma unroll
            for (int mi = 0; mi < 4; mi++) {
                int m0 = wm * 64 + mi * 16;
                af[mi][0] = f2tf32(As[(m0 + g) * AS_STRIDE + kk + t]);
                af[mi][1] = f2tf32(As[(m0 + g + 8) * AS_STRIDE + kk + t]);
                af[mi][2] = f2tf32(As[(m0 + g) * AS_STRIDE + kk + t + 4]);
                af[mi][3] = f2tf32(As[(m0 + g + 8) * AS_STRIDE + kk + t + 4]);
            }
#pragma unroll
            for (int ni = 0; ni < 4; ni++) {
                int n0 = wn * 32 + ni * 8;
                bf[ni][0] = f2tf32(Bs[(kk + t) * BS_STRIDE + n0 + g]);
                bf[ni][1] = f2tf32(Bs[(kk + t + 4) * BS_STRIDE + n0 + g]);
            }
#pragma unroll
            for (int mi = 0; mi < 4; mi++)
#pragma unroll
                for (int ni = 0; ni < 4; ni++) {
                    asm volatile(
                        "mma.sync.aligned.m16n8k8.row.col.f32.tf32.tf32.f32 "
                        "{%0,%1,%2,%3}, {%4,%5,%6,%7}, {%8,%9}, {%0,%1,%2,%3};"
                        : "+f"(acc[mi][ni][0]), "+f"(acc[mi][ni][1]),
                          "+f"(acc[mi][ni][2]), "+f"(acc[mi][ni][3])
                        : "r"(af[mi][0]), "r"(af[mi][1]), "r"(af[mi][2]), "r"(af[mi][3]),
                          "r"(bf[ni][0]), "r"(bf[ni][1]));
                }
        }
        __syncthreads();
    }

#pragma unroll
    for (int mi = 0; mi < 4; mi++) {
#pragma unroll
        for (int ni = 0; ni < 4; ni++) {
            int row0 = bm + wm * 64 + mi * 16 + g;
            int col = bn + wn * 32 + ni * 8 + t * 2;
            *(float2*)&C[(size_t)row0 * ldc + col] =
                make_float2(acc[mi][ni][0], acc[mi][ni][1]);
            *(float2*)&C[(size_t)(row0 + 8) * ldc + col] =
                make_float2(acc[mi][ni][2], acc[mi][ni][3]);
        }
    }
}

// ---------------------------------------------------------------------------
// FUSED attention GEMM: out[b,i,:] = softmax_j(mask(leaky(el_i+er_j))) @ h[b,j,:]
// P is never materialized. A-tile built in smem from adj (cp.async) + el + er:
//   p~ = tf32(exp(e)), unnormalized; per-row sums of p~ accumulated in regs,
//   reduced deterministically, applied in epilogue.
// ---------------------------------------------------------------------------
__global__ __launch_bounds__(256, 2) void fused_attn_gemm_kernel(
    const int* __restrict__ adjg, const float* __restrict__ Hg,
    float* __restrict__ Cg)
{
    extern __shared__ float smem[];
    // layout: As[2][128*36] | Bs[2][32*136] | adj[2][128*32] | srow[128]
    float* As_base = smem;
    float* Bs_base = smem + 2 * AS_TILE;
    int* adj_base = (int*)(smem + 2 * AS_TILE + 2 * BS_TILE);
    float* srow = (float*)(adj_base + 2 * ADJ_TILE);

    const int b = blockIdx.z;
    const int* Aj = adjg + (size_t)b * NN * NN;
    const float* B = Hg + (size_t)b * NN * NF;
    float* C = Cg + (size_t)b * NN * NF;
    const float* el_b = g_el + b * NN;
    const float* er_b = g_er + b * NN;

    const int bm = blockIdx.x * 128;
    const int bn = blockIdx.y * 128;
    const int tid = threadIdx.x;
    const int warp = tid >> 5;
    const int lane = tid & 31;
    const int wm = warp >> 2;
    const int wn = warp & 3;
    const int g = lane >> 2;
    const int t = lane & 3;

    int a_row[4], a_c4[4], b_row[4], b_c4[4];
#pragma unroll
    for (int j = 0; j < 4; j++) {
        int i = tid + j * 256;
        a_row[j] = i >> 3;  a_c4[j] = (i & 7) * 4;
        b_row[j] = i >> 5;  b_c4[j] = (i & 31) * 4;
    }

    // el for this thread's fill rows — loop-invariant
    float elr[4];
#pragma unroll
    for (int j = 0; j < 4; j++) elr[j] = el_b[bm + a_row[j]];

    float psum[4] = {0.f, 0.f, 0.f, 0.f};

    uint32_t adj_u32 = (uint32_t)__cvta_generic_to_shared((void*)adj_base);
    uint32_t bs_u32 = (uint32_t)__cvta_generic_to_shared((void*)Bs_base);

    auto issue_stage = [&](int s, int k0) {
        uint32_t aj = adj_u32 + (uint32_t)(s * ADJ_TILE) * 4u;
        uint32_t bs = bs_u32 + (uint32_t)(s * BS_TILE) * 4u;
#pragma unroll
        for (int j = 0; j < 4; j++)
            cpasync16(aj + (uint32_t)(a_row[j] * ADJ_STRIDE + a_c4[j]) * 4u,
                      &Aj[(size_t)(bm + a_row[j]) * NN + k0 + a_c4[j]]);
#pragma unroll
        for (int j = 0; j < 4; j++)
            cpasync16(bs + (uint32_t)(b_row[j] * BS_STRIDE + b_c4[j]) * 4u,
                      &B[(size_t)(k0 + b_row[j]) * NF + bn + b_c4[j]]);
        asm volatile("cp.async.commit_group;");
    };

    float acc[4][4][4];
#pragma unroll
    for (int mi = 0; mi < 4; mi++)
#pragma unroll
        for (int ni = 0; ni < 4; ni++)
#pragma unroll
            for (int r = 0; r < 4; r++) acc[mi][ni][r] = 0.f;

    issue_stage(0, 0);

    const int niter = NN / 32;
    for (int it = 0; it < niter; it++) {
        const int k0 = it * 32;
        if (it + 1 < niter) {
            issue_stage((it + 1) & 1, (it + 1) * 32);
            asm volatile("cp.async.wait_group 1;");
        } else {
            asm volatile("cp.async.wait_group 0;");
        }
        __syncthreads();

        const int s = it & 1;
        uint32_t* As = (uint32_t*)(As_base + s * AS_TILE);
        const float* Bs = Bs_base + s * BS_TILE;
        const int* adjS = adj_base + s * ADJ_TILE;

        // Build A-tile: p~ = tf32(exp(mask(leaky(el+er))))
#pragma unroll
        for (int j = 0; j < 4; j++) {
            int4 av = *(const int4*)&adjS[a_row[j] * ADJ_STRIDE + a_c4[j]];
            float4 er4 = *(const float4*)&er_b[k0 + a_c4[j]];
            float e0 = elr[j] + er4.x, e1 = elr[j] + er4.y;
            float e2 = elr[j] + er4.z, e3 = elr[j] + er4.w;
            e0 = e0 > 0.f ? e0 : ALPHA * e0;
            e1 = e1 > 0.f ? e1 : ALPHA * e1;
            e2 = e2 > 0.f ? e2 : ALPHA * e2;
            e3 = e3 > 0.f ? e3 : ALPHA * e3;
            e0 = av.x > 0 ? e0 : NEG_BIG;
            e1 = av.y > 0 ? e1 : NEG_BIG;
            e2 = av.z > 0 ? e2 : NEG_BIG;
            e3 = av.w > 0 ? e3 : NEG_BIG;
            uint32_t u0 = f2tf32(__expf(e0));
            uint32_t u1 = f2tf32(__expf(e1));
            uint32_t u2 = f2tf32(__expf(e2));
            uint32_t u3 = f2tf32(__expf(e3));
            *(uint4*)&As[a_row[j] * AS_STRIDE + a_c4[j]] = make_uint4(u0, u1, u2, u3);
            psum[j] += __uint_as_float(u0) + __uint_as_float(u1) +
                       __uint_as_float(u2) + __uint_as_float(u3);
        }
        __syncthreads();

#pragma unroll
        for (int kc = 0; kc < 4; kc++) {
            const int kk = kc * 8;
            uint32_t af[4][4], bf[4][2];
#pragma unroll
            for (int mi = 0; mi < 4; mi++) {
                int m0 = wm * 64 + mi * 16;
                af[mi][0] = As[(m0 + g) * AS_STRIDE + kk + t];
                af[mi][1] = As[(m0 + g + 8) * AS_STRIDE + kk + t];
                af[mi][2] = As[(m0 + g) * AS_STRIDE + kk + t + 4];
                af[mi][3] = As[(m0 + g + 8) * AS_STRIDE + kk + t + 4];
            }
#pragma unroll
            for (int ni = 0; ni < 4; ni++) {
                int n0 = wn * 32 + ni * 8;
                bf[ni][0] = f2tf32(Bs[(kk + t) * BS_STRIDE + n0 + g]);
                bf[ni][1] = f2tf32(Bs[(kk + t + 4) * BS_STRIDE + n0 + g]);
            }
#pragma unroll
            for (int mi = 0; mi < 4; mi++)
#pragma unroll
                for (int ni = 0; ni < 4; ni++) {
                    asm volatile(
                        "mma.sync.aligned.m16n8k8.row.col.f32.tf32.tf32.f32 "
                        "{%0,%1,%2,%3}, {%4,%5,%6,%7}, {%8,%9}, {%0,%1,%2,%3};"
                        : "+f"(acc[mi][ni][0]), "+f"(acc[mi][ni][1]),
                          "+f"(acc[mi][ni][2]), "+f"(acc[mi][ni][3])
                        : "r"(af[mi][0]), "r"(af[mi][1]), "r"(af[mi][2]), "r"(af[mi][3]),
                          "r"(bf[ni][0]), "r"(bf[ni][1]));
                }
        }
        __syncthreads();
    }

    // Deterministic per-row sum: 8 lanes (same row) reduce via bfly shuffles.
#pragma unroll
    for (int j = 0; j < 4; j++) {
        float v = psum[j];
        v += __shfl_xor_sync(0xffffffffu, v, 4);
        v += __shfl_xor_sync(0xffffffffu, v, 2);
        v += __shfl_xor_sync(0xffffffffu, v, 1);
        if ((lane & 7) == 0) srow[a_row[j]] = v;   // a_row[j] distinct across writers
    }
    __syncthreads();

#pragma unroll
    for (int mi = 0; mi < 4; mi++) {
        int r0 = wm * 64 + mi * 16 + g;
        float inv0 = 1.0f / srow[r0];
        float inv8 = 1.0f / srow[r0 + 8];
#pragma unroll
        for (int ni = 0; ni < 4; ni++) {
            int col = bn + wn * 32 + ni * 8 + t * 2;
            *(float2*)&C[(size_t)(bm + r0) * NF + col] =
                make_float2(acc[mi][ni][0] * inv0, acc[mi][ni][1] * inv0);
            *(float2*)&C[(size_t)(bm + r0 + 8) * NF + col] =
                make_float2(acc[mi][ni][2] * inv8, acc[mi][ni][3] * inv8);
        }
    }
}

// ---------------------------------------------------------------------------
// wa[sel][i] = sum_o W[i][o] * a[sel*256 + o]    (exact fp32, tiny)
// ---------------------------------------------------------------------------
__global__ __launch_bounds__(256) void wa_kernel(
    const float* __restrict__ W, const float* __restrict__ a)
{
    int i = blockIdx.x & 255;
    int sel = blockIdx.x >> 8;
    int tid = threadIdx.x;
    float v = W[(size_t)i * NF + tid] * a[sel * NF + tid];
#pragma unroll
    for (int off = 16; off > 0; off >>= 1)
        v += __shfl_xor_sync(0xffffffffu, v, off);
    __shared__ float s[8];
    if ((tid & 31) == 0) s[tid >> 5] = v;
    __syncthreads();
    if (tid == 0) {
        float acc = 0.f;
#pragma unroll
        for (int w = 0; w < 8; w++) acc += s[w];
        g_wa[sel * NF + i] = acc;
    }
}

// ---------------------------------------------------------------------------
// el[row] = x[row,:] . wa_l,  er[row] = x[row,:] . wa_r   (exact fp32)
// ---------------------------------------------------------------------------
__global__ __launch_bounds__(256) void rowdot_x_kernel(const float* __restrict__ x)
{
    int row = blockIdx.x;
    int tid = threadIdx.x;
    float xv = x[(size_t)row * NF + tid];
    float l = xv * g_wa[tid];
    float r = xv * g_wa[NF + tid];
#pragma unroll
    for (int o = 16; o > 0; o >>= 1) {
        l += __shfl_xor_sync(0xffffffffu, l, o);
        r += __shfl_xor_sync(0xffffffffu, r, o);
    }
    __shared__ float sl[8], sr[8];
    if ((tid & 31) == 0) { sl[tid >> 5] = l; sr[tid >> 5] = r; }
    __syncthreads();
    if (tid == 0) {
        float L = 0.f, R = 0.f;
#pragma unroll
        for (int w = 0; w < 8; w++) { L += sl[w]; R += sr[w]; }
        g_el[row] = L;
        g_er[row] = R;
    }
}

// ---------------------------------------------------------------------------
extern "C" void kernel_launch(void* const* d_in, const int* in_sizes, int n_in,
                              void* d_out, int out_size)
{
    const float* x   = (const float*)d_in[0];   // (16,1024,256) f32
    const int*   adj = (const int*)d_in[1];     // (16,1024,1024) i32
    const float* W   = (const float*)d_in[2];   // (256,256) f32
    const float* a   = (const float*)d_in[3];   // (512,1) f32
    float* out = (float*)d_out;                 // (16,1024,256) f32

    float* h;
    cudaGetSymbolAddress((void**)&h, g_h);

    cudaFuncSetAttribute(mma_gemm_kernel,
                         cudaFuncAttributeMaxDynamicSharedMemorySize, G1_SMEM_BYTES);
    cudaFuncSetAttribute(fused_attn_gemm_kernel,
                         cudaFuncAttributeMaxDynamicSharedMemorySize, FU_SMEM_BYTES);

    // 1) wa = W @ [a_l | a_r]   (exact)
    wa_kernel<<<512, 256>>>(W, a);
    // 2) el/er = x @ wa  (exact fp32)
    rowdot_x_kernel<<<NB * NN, 256>>>(x);
    // 3) h = x @ W  (tf32 tensor cores)
    {
        dim3 grid((NB * NN) / 128, NF / 128, 1);
        mma_gemm_kernel<<<grid, 256, G1_SMEM_BYTES>>>(x, W, h, NF);
    }
    // 4) out = softmax(mask(leaky(el+er))) @ h   — fused, P never materialized
    {
        dim3 grid(NN / 128, NF / 128, NB);
        fused_attn_gemm_kernel<<<grid, 256, FU_SMEM_BYTES>>>(adj, h, out);
    }
}

// round 9
// speedup vs baseline: 2.8952x; 1.0150x over previous
#include <cuda_runtime.h>
#include <cstdint>

#define ALPHA 0.2f

#define NB 16
#define NN 1024
#define NF 256

// Scratch (device globals: allocation-free rule)
__device__ float g_h[NB * NN * NF];           // 16 MB: h = x @ W
__device__ float g_el[NB * NN];
__device__ float g_er[NB * NN];
__device__ float g_eel[NB * NN];              // exp(el)
__device__ float g_eel2[NB * NN];             // exp(ALPHA*el)
__device__ float g_eer[NB * NN];              // exp(er)
__device__ float g_eer2[NB * NN];             // exp(ALPHA*er)
__device__ float g_wa[2 * NF];                // W @ a_l, W @ a_r

// ---------------------------------------------------------------------------
// helpers
// ---------------------------------------------------------------------------
__device__ __forceinline__ uint32_t f2tf32(float f) {
    uint32_t r;
    asm("cvt.rna.tf32.f32 %0, %1;" : "=r"(r) : "f"(f));
    return r;
}
__device__ __forceinline__ void cpasync16(uint32_t dst, const void* src) {
    asm volatile("cp.async.cg.shared.global [%0], [%1], 16;" :: "r"(dst), "l"(src));
}

// smem tile geometry (32-bit words)
#define AS_STRIDE 36
#define BS_STRIDE 136
#define ADJ_STRIDE 32
#define AS_TILE (128 * AS_STRIDE)      // 4608
#define BS_TILE (32 * BS_STRIDE)       // 4352
#define ADJ_TILE (128 * ADJ_STRIDE)    // 4096

#define G1_STG (AS_TILE + BS_TILE)
#define G1_SMEM_BYTES (2 * G1_STG * 4)             // 71680

#define FU_WORDS (2 * AS_TILE + 2 * BS_TILE + 2 * ADJ_TILE + 128)
#define FU_SMEM_BYTES (FU_WORDS * 4)               // 104960

// ---------------------------------------------------------------------------
// tf32 tensor-core GEMM, cp.async double-buffered (h = x@W).
// ---------------------------------------------------------------------------
__global__ __launch_bounds__(256, 2) void mma_gemm_kernel(
    const float* __restrict__ A, const float* __restrict__ B,
    float* __restrict__ C, int K)
{
    extern __shared__ float smem[];

    const int lda = K;
    const int ldb = NF;
    const int ldc = NF;

    const int bm = blockIdx.x * 128;
    const int bn = blockIdx.y * 128;
    const int tid = threadIdx.x;
    const int warp = tid >> 5;
    const int lane = tid & 31;
    const int wm = warp >> 2;
    const int wn = warp & 3;
    const int g = lane >> 2;
    const int t = lane & 3;

    int a_row[4], a_c4[4], b_row[4], b_c4[4];
#pragma unroll
    for (int j = 0; j < 4; j++) {
        int i = tid + j * 256;
        a_row[j] = i >> 3;  a_c4[j] = (i & 7) * 4;
        b_row[j] = i >> 5;  b_c4[j] = (i & 31) * 4;
    }

    uint32_t smem_u32 = (uint32_t)__cvta_generic_to_shared((void*)smem);
    const int niter = K / 32;

    auto issue_stage = [&](int s, int k0) {
        uint32_t as_base = smem_u32 + (uint32_t)(s * G1_STG) * 4u;
        uint32_t bs_base = as_base + (uint32_t)AS_TILE * 4u;
#pragma unroll
        for (int j = 0; j < 4; j++)
            cpasync16(as_base + (uint32_t)(a_row[j] * AS_STRIDE + a_c4[j]) * 4u,
                      &A[(size_t)(bm + a_row[j]) * lda + k0 + a_c4[j]]);
#pragma unroll
        for (int j = 0; j < 4; j++)
            cpasync16(bs_base + (uint32_t)(b_row[j] * BS_STRIDE + b_c4[j]) * 4u,
                      &B[(size_t)(k0 + b_row[j]) * ldb + bn + b_c4[j]]);
        asm volatile("cp.async.commit_group;");
    };

    float acc[4][4][4];
#pragma unroll
    for (int mi = 0; mi < 4; mi++)
#pragma unroll
        for (int ni = 0; ni < 4; ni++)
#pragma unroll
            for (int r = 0; r < 4; r++) acc[mi][ni][r] = 0.f;

    issue_stage(0, 0);

    for (int it = 0; it < niter; it++) {
        if (it + 1 < niter) {
            issue_stage((it + 1) & 1, (it + 1) * 32);
            asm volatile("cp.async.wait_group 1;");
        } else {
            asm volatile("cp.async.wait_group 0;");
        }
        __syncthreads();

        const float* As = smem + (it & 1) * G1_STG;
        const float* Bs = As + AS_TILE;

#pragma unroll
        for (int kc = 0; kc < 4; kc++) {
            const int kk = kc * 8;
            uint32_t af[4][4], bf[4][2];
#pragma unroll
            for (int mi = 0; mi < 4; mi++) {
                int m0 = wm * 64 + mi * 16;
                af[mi][0] = f2tf32(As[(m0 + g) * AS_STRIDE + kk + t]);
                af[mi][1] = f2tf32(As[(m0 + g + 8) * AS_STRIDE + kk + t]);
                af[mi][2] = f2tf32(As[(m0 + g) * AS_STRIDE + kk + t + 4]);
                af[mi][3] = f2tf32(As[(m0 + g + 8) * AS_STRIDE + kk + t + 4]);
            }
#pragma unroll
            for (int ni = 0; ni < 4; ni++) {
                int n0 = wn * 32 + ni * 8;
                bf[ni][0] = f2tf32(Bs[(kk + t) * BS_STRIDE + n0 + g]);
                bf[ni][1] = f2tf32(Bs[(kk + t + 4) * BS_STRIDE + n0 + g]);
            }
#pragma unroll
            for (int mi = 0; mi < 4; mi++)
#pragma unroll
                for (int ni = 0; ni < 4; ni++) {
                    asm volatile(
                        "mma.sync.aligned.m16n8k8.row.col.f32.tf32.tf32.f32 "
                        "{%0,%1,%2,%3}, {%4,%5,%6,%7}, {%8,%9}, {%0,%1,%2,%3};"
                        : "+f"(acc[mi][ni][0]), "+f"(acc[mi][ni][1]),
                          "+f"(acc[mi][ni][2]), "+f"(acc[mi][ni][3])
                        : "r"(af[mi][0]), "r"(af[mi][1]), "r"(af[mi][2]), "r"(af[mi][3]),
                          "r"(bf[ni][0]), "r"(bf[ni][1]));
                }
        }
        __syncthreads();
    }

#pragma unroll
    for (int mi = 0; mi < 4; mi++) {
#pragma unroll
        for (int ni = 0; ni < 4; ni++) {
            int row0 = bm + wm * 64 + mi * 16 + g;
            int col = bn + wn * 32 + ni * 8 + t * 2;
            *(float2*)&C[(size_t)row0 * ldc + col] =
                make_float2(acc[mi][ni][0], acc[mi][ni][1]);
            *(float2*)&C[(size_t)(row0 + 8) * ldc + col] =
                make_float2(acc[mi][ni][2], acc[mi][ni][3]);
        }
    }
}

// ---------------------------------------------------------------------------
// FUSED attention GEMM. Factorized exp: no MUFU in the fill.
//   s = el_i + er_j;  p = adj>0 ? (s>0 ? Eel_i*Eer_j : Eel2_i*Eer2_j) : 0
// ---------------------------------------------------------------------------
__global__ __launch_bounds__(256, 2) void fused_attn_gemm_kernel(
    const int* __restrict__ adjg, const float* __restrict__ Hg,
    float* __restrict__ Cg)
{
    extern __shared__ float smem[];
    float* As_base = smem;
    float* Bs_base = smem + 2 * AS_TILE;
    int* adj_base = (int*)(smem + 2 * AS_TILE + 2 * BS_TILE);
    float* srow = (float*)(adj_base + 2 * ADJ_TILE);

    const int b = blockIdx.z;
    const int* Aj = adjg + (size_t)b * NN * NN;
    const float* B = Hg + (size_t)b * NN * NF;
    float* C = Cg + (size_t)b * NN * NF;
    const float* el_b = g_el + b * NN;
    const float* er_b = g_er + b * NN;
    const float* eer_b = g_eer + b * NN;
    const float* eer2_b = g_eer2 + b * NN;

    const int bm = blockIdx.x * 128;
    const int bn = blockIdx.y * 128;
    const int tid = threadIdx.x;
    const int warp = tid >> 5;
    const int lane = tid & 31;
    const int wm = warp >> 2;
    const int wn = warp & 3;
    const int g = lane >> 2;
    const int t = lane & 3;

    int a_row[4], a_c4[4], b_row[4], b_c4[4];
#pragma unroll
    for (int j = 0; j < 4; j++) {
        int i = tid + j * 256;
        a_row[j] = i >> 3;  a_c4[j] = (i & 7) * 4;
        b_row[j] = i >> 5;  b_c4[j] = (i & 31) * 4;
    }

    // loop-invariant per-row values
    float elr[4], eelr[4], eel2r[4];
#pragma unroll
    for (int j = 0; j < 4; j++) {
        elr[j] = el_b[bm + a_row[j]];
        eelr[j] = g_eel[b * NN + bm + a_row[j]];
        eel2r[j] = g_eel2[b * NN + bm + a_row[j]];
    }

    float psum[4] = {0.f, 0.f, 0.f, 0.f};

    uint32_t adj_u32 = (uint32_t)__cvta_generic_to_shared((void*)adj_base);
    uint32_t bs_u32 = (uint32_t)__cvta_generic_to_shared((void*)Bs_base);

    auto issue_stage = [&](int s, int k0) {
        uint32_t aj = adj_u32 + (uint32_t)(s * ADJ_TILE) * 4u;
        uint32_t bs = bs_u32 + (uint32_t)(s * BS_TILE) * 4u;
#pragma unroll
        for (int j = 0; j < 4; j++)
            cpasync16(aj + (uint32_t)(a_row[j] * ADJ_STRIDE + a_c4[j]) * 4u,
                      &Aj[(size_t)(bm + a_row[j]) * NN + k0 + a_c4[j]]);
#pragma unroll
        for (int j = 0; j < 4; j++)
            cpasync16(bs + (uint32_t)(b_row[j] * BS_STRIDE + b_c4[j]) * 4u,
                      &B[(size_t)(k0 + b_row[j]) * NF + bn + b_c4[j]]);
        asm volatile("cp.async.commit_group;");
    };

    float acc[4][4][4];
#pragma unroll
    for (int mi = 0; mi < 4; mi++)
#pragma unroll
        for (int ni = 0; ni < 4; ni++)
#pragma unroll
            for (int r = 0; r < 4; r++) acc[mi][ni][r] = 0.f;

    issue_stage(0, 0);

    const int niter = NN / 32;
    for (int it = 0; it < niter; it++) {
        const int k0 = it * 32;
        if (it + 1 < niter) {
            issue_stage((it + 1) & 1, (it + 1) * 32);
            asm volatile("cp.async.wait_group 1;");
        } else {
            asm volatile("cp.async.wait_group 0;");
        }
        __syncthreads();

        const int s = it & 1;
        uint32_t* As = (uint32_t*)(As_base + s * AS_TILE);
        const float* Bs = Bs_base + s * BS_TILE;
        const int* adjS = adj_base + s * ADJ_TILE;

        // Build A-tile (no exp): p~ = tf32(sel(adj, sel(sign, Eel*Eer, Eel2*Eer2), 0))
#pragma unroll
        for (int j = 0; j < 4; j++) {
            int4 av = *(const int4*)&adjS[a_row[j] * ADJ_STRIDE + a_c4[j]];
            float4 er4 = *(const float4*)&er_b[k0 + a_c4[j]];
            float4 ee4 = *(const float4*)&eer_b[k0 + a_c4[j]];
            float4 ee24 = *(const float4*)&eer2_b[k0 + a_c4[j]];
            bool s0 = (elr[j] + er4.x) > 0.f;
            bool s1 = (elr[j] + er4.y) > 0.f;
            bool s2 = (elr[j] + er4.z) > 0.f;
            bool s3 = (elr[j] + er4.w) > 0.f;
            float p0 = av.x > 0 ? (s0 ? eelr[j] * ee4.x : eel2r[j] * ee24.x) : 0.f;
            float p1 = av.y > 0 ? (s1 ? eelr[j] * ee4.y : eel2r[j] * ee24.y) : 0.f;
            float p2 = av.z > 0 ? (s2 ? eelr[j] * ee4.z : eel2r[j] * ee24.z) : 0.f;
            float p3 = av.w > 0 ? (s3 ? eelr[j] * ee4.w : eel2r[j] * ee24.w) : 0.f;
            uint32_t u0 = f2tf32(p0), u1 = f2tf32(p1);
            uint32_t u2 = f2tf32(p2), u3 = f2tf32(p3);
            *(uint4*)&As[a_row[j] * AS_STRIDE + a_c4[j]] = make_uint4(u0, u1, u2, u3);
            psum[j] += __uint_as_float(u0) + __uint_as_float(u1) +
                       __uint_as_float(u2) + __uint_as_float(u3);
        }
        __syncthreads();

#pragma unroll
        for (int kc = 0; kc < 4; kc++) {
            const int kk = kc * 8;
            uint32_t af[4][4], bf[4][2];
#pragma unroll
            for (int mi = 0; mi < 4; mi++) {
                int m0 = wm * 64 + mi * 16;
                af[mi][0] = As[(m0 + g) * AS_STRIDE + kk + t];
                af[mi][1] = As[(m0 + g + 8) * AS_STRIDE + kk + t];
                af[mi][2] = As[(m0 + g) * AS_STRIDE + kk + t + 4];
                af[mi][3] = As[(m0 + g + 8) * AS_STRIDE + kk + t + 4];
            }
#pragma unroll
            for (int ni = 0; ni < 4; ni++) {
                int n0 = wn * 32 + ni * 8;
                bf[ni][0] = f2tf32(Bs[(kk + t) * BS_STRIDE + n0 + g]);
                bf[ni][1] = f2tf32(Bs[(kk + t + 4) * BS_STRIDE + n0 + g]);
            }
#pragma unroll
            for (int mi = 0; mi < 4; mi++)
#pragma unroll
                for (int ni = 0; ni < 4; ni++) {
                    asm volatile(
                        "mma.sync.aligned.m16n8k8.row.col.f32.tf32.tf32.f32 "
                        "{%0,%1,%2,%3}, {%4,%5,%6,%7}, {%8,%9}, {%0,%1,%2,%3};"
                        : "+f"(acc[mi][ni][0]), "+f"(acc[mi][ni][1]),
                          "+f"(acc[mi][ni][2]), "+f"(acc[mi][ni][3])
                        : "r"(af[mi][0]), "r"(af[mi][1]), "r"(af[mi][2]), "r"(af[mi][3]),
                          "r"(bf[ni][0]), "r"(bf[ni][1]));
                }
        }
        __syncthreads();
    }

    // Deterministic per-row sum: 8 lanes (same row) reduce via bfly shuffles.
#pragma unroll
    for (int j = 0; j < 4; j++) {
        float v = psum[j];
        v += __shfl_xor_sync(0xffffffffu, v, 4);
        v += __shfl_xor_sync(0xffffffffu, v, 2);
        v += __shfl_xor_sync(0xffffffffu, v, 1);
        if ((lane & 7) == 0) srow[a_row[j]] = v;
    }
    __syncthreads();

#pragma unroll
    for (int mi = 0; mi < 4; mi++) {
        int r0 = wm * 64 + mi * 16 + g;
        float inv0 = 1.0f / srow[r0];
        float inv8 = 1.0f / srow[r0 + 8];
#pragma unroll
        for (int ni = 0; ni < 4; ni++) {
            int col = bn + wn * 32 + ni * 8 + t * 2;
            *(float2*)&C[(size_t)(bm + r0) * NF + col] =
                make_float2(acc[mi][ni][0] * inv0, acc[mi][ni][1] * inv0);
            *(float2*)&C[(size_t)(bm + r0 + 8) * NF + col] =
                make_float2(acc[mi][ni][2] * inv8, acc[mi][ni][3] * inv8);
        }
    }
}

// ---------------------------------------------------------------------------
// wa[sel][i] = sum_o W[i][o] * a[sel*256 + o]    (exact fp32, tiny)
// ---------------------------------------------------------------------------
__global__ __launch_bounds__(256) void wa_kernel(
    const float* __restrict__ W, const float* __restrict__ a)
{
    int i = blockIdx.x & 255;
    int sel = blockIdx.x >> 8;
    int tid = threadIdx.x;
    float v = W[(size_t)i * NF + tid] * a[sel * NF + tid];
#pragma unroll
    for (int off = 16; off > 0; off >>= 1)
        v += __shfl_xor_sync(0xffffffffu, v, off);
    __shared__ float s[8];
    if ((tid & 31) == 0) s[tid >> 5] = v;
    __syncthreads();
    if (tid == 0) {
        float acc = 0.f;
#pragma unroll
        for (int w = 0; w < 8; w++) acc += s[w];
        g_wa[sel * NF + i] = acc;
    }
}

// ---------------------------------------------------------------------------
// Warp-per-row: el/er = x . wa  (float4 loads) + exp precomputes.
// 8 rows per block (256 threads), grid = 16384/8 = 2048.
// ---------------------------------------------------------------------------
__global__ __launch_bounds__(256) void rowdot_x_kernel(const float* __restrict__ x)
{
    int row = blockIdx.x * 8 + (threadIdx.x >> 5);
    int lane = threadIdx.x & 31;
    const float* xr = x + (size_t)row * NF;

    float l = 0.f, r = 0.f;
#pragma unroll
    for (int c = 0; c < 2; c++) {
        int idx = (lane + c * 32) * 4;
        float4 xv = *(const float4*)&xr[idx];
        float4 wl = *(const float4*)&g_wa[idx];
        float4 wr = *(const float4*)&g_wa[NF + idx];
        l += xv.x * wl.x + xv.y * wl.y + xv.z * wl.z + xv.w * wl.w;
        r += xv.x * wr.x + xv.y * wr.y + xv.z * wr.z + xv.w * wr.w;
    }
#pragma unroll
    for (int o = 16; o > 0; o >>= 1) {
        l += __shfl_xor_sync(0xffffffffu, l, o);
        r += __shfl_xor_sync(0xffffffffu, r, o);
    }
    if (lane == 0) {
        g_el[row] = l;
        g_er[row] = r;
        g_eel[row] = __expf(l);
        g_eel2[row] = __expf(ALPHA * l);
        g_eer[row] = __expf(r);
        g_eer2[row] = __expf(ALPHA * r);
    }
}

// ---------------------------------------------------------------------------
extern "C" void kernel_launch(void* const* d_in, const int* in_sizes, int n_in,
                              void* d_out, int out_size)
{
    const float* x   = (const float*)d_in[0];   // (16,1024,256) f32
    const int*   adj = (const int*)d_in[1];     // (16,1024,1024) i32
    const float* W   = (const float*)d_in[2];   // (256,256) f32
    const float* a   = (const float*)d_in[3];   // (512,1) f32
    float* out = (float*)d_out;                 // (16,1024,256) f32

    float* h;
    cudaGetSymbolAddress((void**)&h, g_h);

    cudaFuncSetAttribute(mma_gemm_kernel,
                         cudaFuncAttributeMaxDynamicSharedMemorySize, G1_SMEM_BYTES);
    cudaFuncSetAttribute(fused_attn_gemm_kernel,
                         cudaFuncAttributeMaxDynamicSharedMemorySize, FU_SMEM_BYTES);

    // 1) wa = W @ [a_l | a_r]   (exact)
    wa_kernel<<<512, 256>>>(W, a);
    // 2) el/er = x @ wa (+ exp precomputes, exact fp32)
    rowdot_x_kernel<<<(NB * NN) / 8, 256>>>(x);
    // 3) h = x @ W  (tf32 tensor cores)
    {
        dim3 grid((NB * NN) / 128, NF / 128, 1);
        mma_gemm_kernel<<<grid, 256, G1_SMEM_BYTES>>>(x, W, h, NF);
    }
    // 4) out = softmax(mask(leaky(el+er))) @ h   — fused, factorized exp
    {
        dim3 grid(NN / 128, NF / 128, NB);
        fused_attn_gemm_kernel<<<grid, 256, FU_SMEM_BYTES>>>(adj, h, out);
    }
}

// round 12
// speedup vs baseline: 2.9874x; 1.0319x over previous
#include <cuda_runtime.h>
#include <cstdint>

#define ALPHA 0.2f

#define NB 16
#define NN 1024
#define NF 256

// Scratch (device globals: allocation-free rule)
__device__ float g_h[NB * NN * NF];           // 16 MB: h = x @ W
__device__ float g_el[NB * NN];
__device__ float g_er[NB * NN];
__device__ float g_eel[NB * NN];              // exp(el)
__device__ float g_eel2[NB * NN];             // exp(ALPHA*el)
__device__ float g_eer[NB * NN];              // exp(er)
__device__ float g_eer2[NB * NN];             // exp(ALPHA*er)
__device__ float g_wa[2 * NF];                // W @ a_l, W @ a_r

// ---------------------------------------------------------------------------
// helpers
// ---------------------------------------------------------------------------
__device__ __forceinline__ uint32_t f2tf32(float f) {
    uint32_t r;
    asm("cvt.rna.tf32.f32 %0, %1;" : "=r"(r) : "f"(f));
    return r;
}
__device__ __forceinline__ void cpasync16(uint32_t dst, const void* src) {
    asm volatile("cp.async.cg.shared.global [%0], [%1], 16;" :: "r"(dst), "l"(src));
}

// ---- h = x@W GEMM smem geometry (unchanged from R9) ----
#define AS_STRIDE 36
#define BS_STRIDE 136
#define AS_TILE (128 * AS_STRIDE)      // 4608
#define BS_TILE (32 * BS_STRIDE)       // 4352
#define G1_STG (AS_TILE + BS_TILE)
#define G1_SMEM_BYTES (2 * G1_STG * 4)             // 71680

// ---- fused GEMM smem geometry: block tile 128x256, 512 threads ----
#define FBS_STRIDE 264
#define FBS_TILE (32 * FBS_STRIDE)     // 8448
#define ADJ_STRIDE 32
#define ADJ_TILE (128 * ADJ_STRIDE)    // 4096
#define FU_WORDS (2 * AS_TILE + 2 * FBS_TILE + 2 * ADJ_TILE + 128)  // 34432
#define FU_SMEM_BYTES (FU_WORDS * 4)   // 137728

// ---------------------------------------------------------------------------
// tf32 tensor-core GEMM, cp.async double-buffered (h = x@W).
// ---------------------------------------------------------------------------
__global__ __launch_bounds__(256, 2) void mma_gemm_kernel(
    const float* __restrict__ A, const float* __restrict__ B,
    float* __restrict__ C, int K)
{
    extern __shared__ float smem[];

    const int lda = K;
    const int ldb = NF;
    const int ldc = NF;

    const int bm = blockIdx.x * 128;
    const int bn = blockIdx.y * 128;
    const int tid = threadIdx.x;
    const int warp = tid >> 5;
    const int lane = tid & 31;
    const int wm = warp >> 2;
    const int wn = warp & 3;
    const int g = lane >> 2;
    const int t = lane & 3;

    int a_row[4], a_c4[4], b_row[4], b_c4[4];
#pragma unroll
    for (int j = 0; j < 4; j++) {
        int i = tid + j * 256;
        a_row[j] = i >> 3;  a_c4[j] = (i & 7) * 4;
        b_row[j] = i >> 5;  b_c4[j] = (i & 31) * 4;
    }

    uint32_t smem_u32 = (uint32_t)__cvta_generic_to_shared((void*)smem);
    const int niter = K / 32;

    auto issue_stage = [&](int s, int k0) {
        uint32_t as_base = smem_u32 + (uint32_t)(s * G1_STG) * 4u;
        uint32_t bs_base = as_base + (uint32_t)AS_TILE * 4u;
#pragma unroll
        for (int j = 0; j < 4; j++)
            cpasync16(as_base + (uint32_t)(a_row[j] * AS_STRIDE + a_c4[j]) * 4u,
                      &A[(size_t)(bm + a_row[j]) * lda + k0 + a_c4[j]]);
#pragma unroll
        for (int j = 0; j < 4; j++)
            cpasync16(bs_base + (uint32_t)(b_row[j] * BS_STRIDE + b_c4[j]) * 4u,
                      &B[(size_t)(k0 + b_row[j]) * ldb + bn + b_c4[j]]);
        asm volatile("cp.async.commit_group;");
    };

    float acc[4][4][4];
#pragma unroll
    for (int mi = 0; mi < 4; mi++)
#pragma unroll
        for (int ni = 0; ni < 4; ni++)
#pragma unroll
            for (int r = 0; r < 4; r++) acc[mi][ni][r] = 0.f;

    issue_stage(0, 0);

    for (int it = 0; it < niter; it++) {
        if (it + 1 < niter) {
            issue_stage((it + 1) & 1, (it + 1) * 32);
            asm volatile("cp.async.wait_group 1;");
        } else {
            asm volatile("cp.async.wait_group 0;");
        }
        __syncthreads();

        const float* As = smem + (it & 1) * G1_STG;
        const float* Bs = As + AS_TILE;

#pragma unroll
        for (int kc = 0; kc < 4; kc++) {
            const int kk = kc * 8;
            uint32_t af[4][4], bf[4][2];
#pragma unroll
            for (int mi = 0; mi < 4; mi++) {
                int m0 = wm * 64 + mi * 16;
                af[mi][0] = f2tf32(As[(m0 + g) * AS_STRIDE + kk + t]);
                af[mi][1] = f2tf32(As[(m0 + g + 8) * AS_STRIDE + kk + t]);
                af[mi][2] = f2tf32(As[(m0 + g) * AS_STRIDE + kk + t + 4]);
                af[mi][3] = f2tf32(As[(m0 + g + 8) * AS_STRIDE + kk + t + 4]);
            }
#pragma unroll
            for (int ni = 0; ni < 4; ni++) {
                int n0 = wn * 32 + ni * 8;
                bf[ni][0] = f2tf32(Bs[(kk + t) * BS_STRIDE + n0 + g]);
                bf[ni][1] = f2tf32(Bs[(kk + t + 4) * BS_STRIDE + n0 + g]);
            }
#pragma unroll
            for (int mi = 0; mi < 4; mi++)
#pragma unroll
                for (int ni = 0; ni < 4; ni++) {
                    asm volatile(
                        "mma.sync.aligned.m16n8k8.row.col.f32.tf32.tf32.f32 "
                        "{%0,%1,%2,%3}, {%4,%5,%6,%7}, {%8,%9}, {%0,%1,%2,%3};"
                        : "+f"(acc[mi][ni][0]), "+f"(acc[mi][ni][1]),
                          "+f"(acc[mi][ni][2]), "+f"(acc[mi][ni][3])
                        : "r"(af[mi][0]), "r"(af[mi][1]), "r"(af[mi][2]), "r"(af[mi][3]),
                          "r"(bf[ni][0]), "r"(bf[ni][1]));
                }
        }
        __syncthreads();
    }

#pragma unroll
    for (int mi = 0; mi < 4; mi++) {
#pragma unroll
        for (int ni = 0; ni < 4; ni++) {
            int row0 = bm + wm * 64 + mi * 16 + g;
            int col = bn + wn * 32 + ni * 8 + t * 2;
            *(float2*)&C[(size_t)row0 * ldc + col] =
                make_float2(acc[mi][ni][0], acc[mi][ni][1]);
            *(float2*)&C[(size_t)(row0 + 8) * ldc + col] =
                make_float2(acc[mi][ni][2], acc[mi][ni][3]);
        }
    }
}

// ---------------------------------------------------------------------------
// FUSED attention GEMM, block tile 128x256, 512 threads (16 warps, 2x8).
// A-tile (softmax numerators) built ONCE per M-tile and shared by all of N.
// ---------------------------------------------------------------------------
__global__ __launch_bounds__(512, 1) void fused_attn_gemm_kernel(
    const int* __restrict__ adjg, const float* __restrict__ Hg,
    float* __restrict__ Cg)
{
    extern __shared__ float smem[];
    float* As_base = smem;                                  // 2 x 128x36
    float* Bs_base = smem + 2 * AS_TILE;                    // 2 x 32x264
    int* adj_base = (int*)(smem + 2 * AS_TILE + 2 * FBS_TILE);  // 2 x 128x32
    float* srow = (float*)(adj_base + 2 * ADJ_TILE);        // 128

    const int b = blockIdx.z;
    const int* Aj = adjg + (size_t)b * NN * NN;
    const float* B = Hg + (size_t)b * NN * NF;
    float* C = Cg + (size_t)b * NN * NF;
    const float* el_b = g_el + b * NN;
    const float* er_b = g_er + b * NN;
    const float* eer_b = g_eer + b * NN;
    const float* eer2_b = g_eer2 + b * NN;

    const int bm = blockIdx.x * 128;
    const int tid = threadIdx.x;
    const int warp = tid >> 5;
    const int lane = tid & 31;
    const int wm = warp >> 3;        // 0..1   (M)
    const int wn = warp & 7;         // 0..7   (N)
    const int g = lane >> 2;
    const int t = lane & 3;

    // A/adj fill coords: 1024 vec4 slots / 512 threads = 2 each
    int a_row[2], a_c4[2];
#pragma unroll
    for (int j = 0; j < 2; j++) {
        int i = tid + j * 512;
        a_row[j] = i >> 3;  a_c4[j] = (i & 7) * 4;
    }
    // B fill coords: 32x256 = 2048 vec4 / 512 = 4 each
    int b_row[4], b_c4[4];
#pragma unroll
    for (int j = 0; j < 4; j++) {
        int i = tid + j * 512;
        b_row[j] = i >> 6;  b_c4[j] = (i & 63) * 4;
    }

    // loop-invariant per-row values
    float elr[2], eelr[2], eel2r[2];
#pragma unroll
    for (int j = 0; j < 2; j++) {
        elr[j] = el_b[bm + a_row[j]];
        eelr[j] = g_eel[b * NN + bm + a_row[j]];
        eel2r[j] = g_eel2[b * NN + bm + a_row[j]];
    }

    float psum[2] = {0.f, 0.f};

    uint32_t adj_u32 = (uint32_t)__cvta_generic_to_shared((void*)adj_base);
    uint32_t bs_u32 = (uint32_t)__cvta_generic_to_shared((void*)Bs_base);

    auto issue_stage = [&](int s, int k0) {
        uint32_t aj = adj_u32 + (uint32_t)(s * ADJ_TILE) * 4u;
        uint32_t bs = bs_u32 + (uint32_t)(s * FBS_TILE) * 4u;
#pragma unroll
        for (int j = 0; j < 2; j++)
            cpasync16(aj + (uint32_t)(a_row[j] * ADJ_STRIDE + a_c4[j]) * 4u,
                      &Aj[(size_t)(bm + a_row[j]) * NN + k0 + a_c4[j]]);
#pragma unroll
        for (int j = 0; j < 4; j++)
            cpasync16(bs + (uint32_t)(b_row[j] * FBS_STRIDE + b_c4[j]) * 4u,
                      &B[(size_t)(k0 + b_row[j]) * NF + b_c4[j]]);
        asm volatile("cp.async.commit_group;");
    };

    float acc[4][4][4];
#pragma unroll
    for (int mi = 0; mi < 4; mi++)
#pragma unroll
        for (int ni = 0; ni < 4; ni++)
#pragma unroll
            for (int r = 0; r < 4; r++) acc[mi][ni][r] = 0.f;

    issue_stage(0, 0);

    const int niter = NN / 32;
    for (int it = 0; it < niter; it++) {
        const int k0 = it * 32;
        if (it + 1 < niter) {
            issue_stage((it + 1) & 1, (it + 1) * 32);
            asm volatile("cp.async.wait_group 1;");
        } else {
            asm volatile("cp.async.wait_group 0;");
        }
        __syncthreads();

        const int s = it & 1;
        uint32_t* As = (uint32_t*)(As_base + s * AS_TILE);
        const float* Bs = Bs_base + s * FBS_TILE;
        const int* adjS = adj_base + s * ADJ_TILE;

        // Build A-tile (once for all N): p~ = tf32(sel(adj, Eel*Eer | Eel2*Eer2, 0))
#pragma unroll
        for (int j = 0; j < 2; j++) {
            int4 av = *(const int4*)&adjS[a_row[j] * ADJ_STRIDE + a_c4[j]];
            float4 er4 = *(const float4*)&er_b[k0 + a_c4[j]];
            float4 ee4 = *(const float4*)&eer_b[k0 + a_c4[j]];
            float4 ee24 = *(const float4*)&eer2_b[k0 + a_c4[j]];
            bool s0 = (elr[j] + er4.x) > 0.f;
            bool s1 = (elr[j] + er4.y) > 0.f;
            bool s2 = (elr[j] + er4.z) > 0.f;
            bool s3 = (elr[j] + er4.w) > 0.f;
            float p0 = av.x > 0 ? (s0 ? eelr[j] * ee4.x : eel2r[j] * ee24.x) : 0.f;
            float p1 = av.y > 0 ? (s1 ? eelr[j] * ee4.y : eel2r[j] * ee24.y) : 0.f;
            float p2 = av.z > 0 ? (s2 ? eelr[j] * ee4.z : eel2r[j] * ee24.z) : 0.f;
            float p3 = av.w > 0 ? (s3 ? eelr[j] * ee4.w : eel2r[j] * ee24.w) : 0.f;
            uint32_t u0 = f2tf32(p0), u1 = f2tf32(p1);
            uint32_t u2 = f2tf32(p2), u3 = f2tf32(p3);
            *(uint4*)&As[a_row[j] * AS_STRIDE + a_c4[j]] = make_uint4(u0, u1, u2, u3);
            psum[j] += __uint_as_float(u0) + __uint_as_float(u1) +
                       __uint_as_float(u2) + __uint_as_float(u3);
        }
        __syncthreads();

#pragma unroll
        for (int kc = 0; kc < 4; kc++) {
            const int kk = kc * 8;
            uint32_t af[4][4], bf[4][2];
#pragma unroll
            for (int mi = 0; mi < 4; mi++) {
                int m0 = wm * 64 + mi * 16;
                af[mi][0] = As[(m0 + g) * AS_STRIDE + kk + t];
                af[mi][1] = As[(m0 + g + 8) * AS_STRIDE + kk + t];
                af[mi][2] = As[(m0 + g) * AS_STRIDE + kk + t + 4];
                af[mi][3] = As[(m0 + g + 8) * AS_STRIDE + kk + t + 4];
            }
#pragma unroll
            for (int ni = 0; ni < 4; ni++) {
                int n0 = wn * 32 + ni * 8;
                bf[ni][0] = f2tf32(Bs[(kk + t) * FBS_STRIDE + n0 + g]);
                bf[ni][1] = f2tf32(Bs[(kk + t + 4) * FBS_STRIDE + n0 + g]);
            }
#pragma unroll
            for (int mi = 0; mi < 4; mi++)
#pragma unroll
                for (int ni = 0; ni < 4; ni++) {
                    asm volatile(
                        "mma.sync.aligned.m16n8k8.row.col.f32.tf32.tf32.f32 "
                        "{%0,%1,%2,%3}, {%4,%5,%6,%7}, {%8,%9}, {%0,%1,%2,%3};"
                        : "+f"(acc[mi][ni][0]), "+f"(acc[mi][ni][1]),
                          "+f"(acc[mi][ni][2]), "+f"(acc[mi][ni][3])
                        : "r"(af[mi][0]), "r"(af[mi][1]), "r"(af[mi][2]), "r"(af[mi][3]),
                          "r"(bf[ni][0]), "r"(bf[ni][1]));
                }
        }
        __syncthreads();
    }

    // Deterministic per-row sum: each As row was filled by 8 consecutive lanes.
#pragma unroll
    for (int j = 0; j < 2; j++) {
        float v = psum[j];
        v += __shfl_xor_sync(0xffffffffu, v, 4);
        v += __shfl_xor_sync(0xffffffffu, v, 2);
        v += __shfl_xor_sync(0xffffffffu, v, 1);
        if ((lane & 7) == 0) srow[a_row[j]] = v;
    }
    __syncthreads();

#pragma unroll
    for (int mi = 0; mi < 4; mi++) {
        int r0 = wm * 64 + mi * 16 + g;
        float inv0 = 1.0f / srow[r0];
        float inv8 = 1.0f / srow[r0 + 8];
#pragma unroll
        for (int ni = 0; ni < 4; ni++) {
            int col = wn * 32 + ni * 8 + t * 2;
            *(float2*)&C[(size_t)(bm + r0) * NF + col] =
                make_float2(acc[mi][ni][0] * inv0, acc[mi][ni][1] * inv0);
            *(float2*)&C[(size_t)(bm + r0 + 8) * NF + col] =
                make_float2(acc[mi][ni][2] * inv8, acc[mi][ni][3] * inv8);
        }
    }
}

// ---------------------------------------------------------------------------
// wa[sel][i] = sum_o W[i][o] * a[sel*256 + o]    (exact fp32, tiny)
// ---------------------------------------------------------------------------
__global__ __launch_bounds__(256) void wa_kernel(
    const float* __restrict__ W, const float* __restrict__ a)
{
    int i = blockIdx.x & 255;
    int sel = blockIdx.x >> 8;
    int tid = threadIdx.x;
    float v = W[(size_t)i * NF + tid] * a[sel * NF + tid];
#pragma unroll
    for (int off = 16; off > 0; off >>= 1)
        v += __shfl_xor_sync(0xffffffffu, v, off);
    __shared__ float s[8];
    if ((tid & 31) == 0) s[tid >> 5] = v;
    __syncthreads();
    if (tid == 0) {
        float acc = 0.f;
#pragma unroll
        for (int w = 0; w < 8; w++) acc += s[w];
        g_wa[sel * NF + i] = acc;
    }
}

// ---------------------------------------------------------------------------
// Warp-per-row: el/er = x . wa  (float4 loads) + exp precomputes.
// ---------------------------------------------------------------------------
__global__ __launch_bounds__(256) void rowdot_x_kernel(const float* __restrict__ x)
{
    int row = blockIdx.x * 8 + (threadIdx.x >> 5);
    int lane = threadIdx.x & 31;
    const float* xr = x + (size_t)row * NF;

    float l = 0.f, r = 0.f;
#pragma unroll
    for (int c = 0; c < 2; c++) {
        int idx = (lane + c * 32) * 4;
        float4 xv = *(const float4*)&xr[idx];
        float4 wl = *(const float4*)&g_wa[idx];
        float4 wr = *(const float4*)&g_wa[NF + idx];
        l += xv.x * wl.x + xv.y * wl.y + xv.z * wl.z + xv.w * wl.w;
        r += xv.x * wr.x + xv.y * wr.y + xv.z * wr.z + xv.w * wr.w;
    }
#pragma unroll
    for (int o = 16; o > 0; o >>= 1) {
        l += __shfl_xor_sync(0xffffffffu, l, o);
        r += __shfl_xor_sync(0xffffffffu, r, o);
    }
    if (lane == 0) {
        g_el[row] = l;
        g_er[row] = r;
        g_eel[row] = __expf(l);
        g_eel2[row] = __expf(ALPHA * l);
        g_eer[row] = __expf(r);
        g_eer2[row] = __expf(ALPHA * r);
    }
}

// ---------------------------------------------------------------------------
extern "C" void kernel_launch(void* const* d_in, const int* in_sizes, int n_in,
                              void* d_out, int out_size)
{
    const float* x   = (const float*)d_in[0];   // (16,1024,256) f32
    const int*   adj = (const int*)d_in[1];     // (16,1024,1024) i32
    const float* W   = (const float*)d_in[2];   // (256,256) f32
    const float* a   = (const float*)d_in[3];   // (512,1) f32
    float* out = (float*)d_out;                 // (16,1024,256) f32

    float* h;
    cudaGetSymbolAddress((void**)&h, g_h);

    cudaFuncSetAttribute(mma_gemm_kernel,
                         cudaFuncAttributeMaxDynamicSharedMemorySize, G1_SMEM_BYTES);
    cudaFuncSetAttribute(fused_attn_gemm_kernel,
                         cudaFuncAttributeMaxDynamicSharedMemorySize, FU_SMEM_BYTES);

    // 1) wa = W @ [a_l | a_r]   (exact)
    wa_kernel<<<512, 256>>>(W, a);
    // 2) el/er = x @ wa (+ exp precomputes, exact fp32)
    rowdot_x_kernel<<<(NB * NN) / 8, 256>>>(x);
    // 3) h = x @ W  (tf32 tensor cores)
    {
        dim3 grid((NB * NN) / 128, NF / 128, 1);
        mma_gemm_kernel<<<grid, 256, G1_SMEM_BYTES>>>(x, W, h, NF);
    }
    // 4) out = softmax(mask(leaky(el+er))) @ h — fused, 128x256 block tile
    {
        dim3 grid(NN / 128, 1, NB);
        fused_attn_gemm_kernel<<<grid, 512, FU_SMEM_BYTES>>>(adj, h, out);
    }
}